// round 11
// baseline (speedup 1.0000x reference)
#include <cuda_runtime.h>
#include <cuda_bf16.h>
#include <math.h>
#include <stdint.h>

typedef long long LL;
typedef __nv_bfloat16 bf16;

// ---------------------------------------------------------------------------
// GlobalAttention (Luong general), B=32, T=S=D=1024, fp32 in/out.
// mma.sync (HMMA) bf16 split-GEMM: 3-product hi/lo emulation of fp32.
// (tcgen05 unavailable: harness compiles for plain sm_103, not sm_103a.)
//
//   1. h_t   = input @ W_in^T            -> split bf16 (g_ht_*)
//   2. align = h_t[b] @ context[b]^T     -> fp32 scores (g_sc)
//   3. probs = softmax(align)            -> d_out[T,B,S] + split bf16 (g_p_*)
//   4. c     = probs[b] @ context[b]     -> split bf16 (g_c_*)   (uses ctx^T)
//   5. attn  = tanh([c,input] @ W_out^T) -> d_out[T,B,D]
// ---------------------------------------------------------------------------

// ---- scratch (__device__ globals: allocation is forbidden) ----
__device__ bf16 g_in_hi[33554432],  g_in_lo[33554432];   // input  [B*T, D]
__device__ bf16 g_ctx_hi[33554432], g_ctx_lo[33554432];  // context[B, S, D]
__device__ bf16 g_ctT_hi[33554432], g_ctT_lo[33554432];  // context^T [B, D, S]
__device__ bf16 g_ht_hi[33554432],  g_ht_lo[33554432];   // h_t [B*T, D]
__device__ bf16 g_p_hi[33554432],   g_p_lo[33554432];    // probs [B*T, S]
__device__ bf16 g_c_hi[33554432],   g_c_lo[33554432];    // c [B*T, D]
__device__ bf16 g_win_hi[1048576],  g_win_lo[1048576];   // W_in [D, D]
__device__ bf16 g_wo_hi[2097152],   g_wo_lo[2097152];    // W_out [D, 2D]
__device__ float g_sc[33554432];                          // raw scores [B,T,S]

// ---- low-level helpers ----
__device__ __forceinline__ uint32_t smem_u32(const void* p) {
    uint32_t a;
    asm("{ .reg .u64 t; cvta.to.shared.u64 t, %1; cvt.u32.u64 %0, t; }"
        : "=r"(a) : "l"(p));
    return a;
}
__device__ __forceinline__ void cp16(uint32_t dst, const void* src) {
    asm volatile("cp.async.cg.shared.global [%0], [%1], 16;"
                 :: "r"(dst), "l"(src) : "memory");
}
__device__ __forceinline__ void ldsm_x4(uint32_t* r, uint32_t addr) {
    asm volatile("ldmatrix.sync.aligned.m8n8.x4.shared.b16 {%0,%1,%2,%3}, [%4];"
                 : "=r"(r[0]), "=r"(r[1]), "=r"(r[2]), "=r"(r[3]) : "r"(addr));
}
__device__ __forceinline__ void ldsm_x2(uint32_t* r, uint32_t addr) {
    asm volatile("ldmatrix.sync.aligned.m8n8.x2.shared.b16 {%0,%1}, [%2];"
                 : "=r"(r[0]), "=r"(r[1]) : "r"(addr));
}
__device__ __forceinline__ void mma16816(float* c, const uint32_t* a, const uint32_t* b) {
    asm volatile(
        "mma.sync.aligned.m16n8k16.row.col.f32.bf16.bf16.f32 "
        "{%0,%1,%2,%3}, {%4,%5,%6,%7}, {%8,%9}, {%0,%1,%2,%3};"
        : "+f"(c[0]), "+f"(c[1]), "+f"(c[2]), "+f"(c[3])
        : "r"(a[0]), "r"(a[1]), "r"(a[2]), "r"(a[3]), "r"(b[0]), "r"(b[1]));
}

#define LDKE 40                       // smem row stride in elements (80 B)
#define TILE_ELE (128 * LDKE)         // 5120 elems = 10240 B per tile

// ---------------------------------------------------------------------------
// Generic NT split-GEMM: C[128,128] tile = sum of 3 hi/lo products, nseg K-segs.
// A [M,K] k-major (ld lda), B [N,K] k-major (ld ldb). BK=32, double-buffered
// cp.async pipeline, 8 warps of 64x32, mma.m16n8k16 bf16.
// MODE 0: fp32 C.  MODE 1: split bf16 (Chi,Clo).  MODE 2: tanh -> fp32 C.
// ---------------------------------------------------------------------------
template<int MODE>
__global__ __launch_bounds__(256)
void mma_nt(const bf16* __restrict__ Ahi, const bf16* __restrict__ Alo, int lda, LL sA,
            const bf16* __restrict__ Bhi, const bf16* __restrict__ Blo, int ldb, LL sB,
            const bf16* __restrict__ A2hi, const bf16* __restrict__ A2lo, int lda2, LL sA2,
            const bf16* __restrict__ B2hi, const bf16* __restrict__ B2lo, int ldb2, LL sB2,
            float* __restrict__ C, bf16* __restrict__ Chi, bf16* __restrict__ Clo,
            int ldc, LL sC, int K, int nseg)
{
    // 16B alignment is REQUIRED for cp.async.16 / ldmatrix targets.
    __shared__ __align__(16) bf16 smA[2][TILE_ELE];
    __shared__ __align__(16) bf16 smB[2][TILE_ELE];

    const int tid = threadIdx.x;
    const int wid = tid >> 5, lane = tid & 31;
    const int warp_m = wid >> 2;         // 0..1
    const int warp_n = wid & 3;          // 0..3
    const int bz = blockIdx.z;
    const int rowBase = blockIdx.y * 128;
    const int colBase = blockIdx.x * 128;

    const uint32_t baseA0 = smem_u32(smA);
    const uint32_t baseB0 = smem_u32(smB);

    float acc[4][4][4];
#pragma unroll
    for (int mt = 0; mt < 4; ++mt)
#pragma unroll
        for (int nt = 0; nt < 4; ++nt)
#pragma unroll
            for (int k = 0; k < 4; ++k) acc[mt][nt][k] = 0.f;

    const int K32 = K >> 5;
    const int nch = 3 * nseg * K32;

    // issue cp.async loads for chunk id into buffer id&1
    auto load_chunk = [&](int id) {
        const int p = id / (nseg * K32);
        const int r0 = id - p * (nseg * K32);
        const int s = r0 / K32;
        const int k0 = (r0 - s * K32) << 5;
        const bf16* pA = (s == 0) ? ((p < 2) ? Ahi : Alo) : ((p < 2) ? A2hi : A2lo);
        const bf16* pB = (s == 0) ? ((p != 1) ? Bhi : Blo) : ((p != 1) ? B2hi : B2lo);
        const int ldA = (s == 0) ? lda : lda2;
        const int ldB = (s == 0) ? ldb : ldb2;
        const LL  sAx = (s == 0) ? sA : sA2;
        const LL  sBx = (s == 0) ? sB : sB2;
        const bf16* Ap = pA + (LL)bz * sAx + (LL)rowBase * ldA + k0;
        const bf16* Bp = pB + (LL)bz * sBx + (LL)colBase * ldB + k0;
        const int buf = id & 1;
        const uint32_t dA = baseA0 + buf * (TILE_ELE * 2);
        const uint32_t dB = baseB0 + buf * (TILE_ELE * 2);
#pragma unroll
        for (int j = 0; j < 2; ++j) {
            const int cid = j * 256 + tid;         // 0..511
            const int rr = cid >> 2, kb = cid & 3; // row, 16B block
            cp16(dA + (uint32_t)(rr * LDKE + kb * 8) * 2, Ap + (LL)rr * ldA + kb * 8);
        }
#pragma unroll
        for (int j = 0; j < 2; ++j) {
            const int cid = j * 256 + tid;
            const int rr = cid >> 2, kb = cid & 3;
            cp16(dB + (uint32_t)(rr * LDKE + kb * 8) * 2, Bp + (LL)rr * ldB + kb * 8);
        }
        asm volatile("cp.async.commit_group;" ::: "memory");
    };

    load_chunk(0);

#pragma unroll 1
    for (int i = 0; i < nch; ++i) {
        if (i + 1 < nch) {
            load_chunk(i + 1);
            asm volatile("cp.async.wait_group 1;" ::: "memory");
        } else {
            asm volatile("cp.async.wait_group 0;" ::: "memory");
        }
        __syncthreads();

        const int buf = i & 1;
        const uint32_t bA = baseA0 + buf * (TILE_ELE * 2);
        const uint32_t bB = baseB0 + buf * (TILE_ELE * 2);

#pragma unroll
        for (int ks = 0; ks < 2; ++ks) {
            uint32_t af[4][4], bfr[4][2];
#pragma unroll
            for (int mt = 0; mt < 4; ++mt) {
                const int row = warp_m * 64 + mt * 16 + (lane & 15);
                ldsm_x4(af[mt], bA + (uint32_t)(row * LDKE + ks * 16 + (lane >> 4) * 8) * 2);
            }
#pragma unroll
            for (int nt = 0; nt < 4; ++nt) {
                const int row = warp_n * 32 + nt * 8 + (lane & 7);
                ldsm_x2(bfr[nt], bB + (uint32_t)(row * LDKE + ks * 16 + ((lane >> 3) & 1) * 8) * 2);
            }
#pragma unroll
            for (int mt = 0; mt < 4; ++mt)
#pragma unroll
                for (int nt = 0; nt < 4; ++nt)
                    mma16816(acc[mt][nt], af[mt], bfr[nt]);
        }
        __syncthreads();
    }

    // ---- epilogue ----
    const int rrow = rowBase + warp_m * 64 + (lane >> 2);
    const int ccol = colBase + warp_n * 32 + (lane & 3) * 2;
#pragma unroll
    for (int mt = 0; mt < 4; ++mt) {
#pragma unroll
        for (int nt = 0; nt < 4; ++nt) {
            const int r0 = rrow + mt * 16;
            const int cc = ccol + nt * 8;
            float v0 = acc[mt][nt][0], v1 = acc[mt][nt][1];
            float v2 = acc[mt][nt][2], v3 = acc[mt][nt][3];
            if (MODE == 2) {
                v0 = tanhf(v0); v1 = tanhf(v1); v2 = tanhf(v2); v3 = tanhf(v3);
            }
            if (MODE == 0 || MODE == 2) {
                float* Cr = C + (LL)bz * sC;
                *(float2*)(Cr + (LL)r0 * ldc + cc)       = make_float2(v0, v1);
                *(float2*)(Cr + (LL)(r0 + 8) * ldc + cc) = make_float2(v2, v3);
            } else {
                bf16 h0 = __float2bfloat16(v0), h1 = __float2bfloat16(v1);
                bf16 h2 = __float2bfloat16(v2), h3 = __float2bfloat16(v3);
                bf16 l0 = __float2bfloat16(v0 - __bfloat162float(h0));
                bf16 l1 = __float2bfloat16(v1 - __bfloat162float(h1));
                bf16 l2 = __float2bfloat16(v2 - __bfloat162float(h2));
                bf16 l3 = __float2bfloat16(v3 - __bfloat162float(h3));
                bf16* Hr = Chi + (LL)bz * sC;
                bf16* Lr = Clo + (LL)bz * sC;
                __nv_bfloat162 t;
                t.x = h0; t.y = h1; *(__nv_bfloat162*)(Hr + (LL)r0 * ldc + cc) = t;
                t.x = h2; t.y = h3; *(__nv_bfloat162*)(Hr + (LL)(r0 + 8) * ldc + cc) = t;
                t.x = l0; t.y = l1; *(__nv_bfloat162*)(Lr + (LL)r0 * ldc + cc) = t;
                t.x = l2; t.y = l3; *(__nv_bfloat162*)(Lr + (LL)(r0 + 8) * ldc + cc) = t;
            }
        }
    }
}

// ---------------------------------------------------------------------------
// fp32 -> bf16 hi/lo split, float4-vectorized
// ---------------------------------------------------------------------------
__global__ __launch_bounds__(256)
void split_kernel(const float* __restrict__ src, bf16* __restrict__ hi,
                  bf16* __restrict__ lo, int n4)
{
    int idx = blockIdx.x * 256 + threadIdx.x;
    if (idx < n4) {
        float4 v = ((const float4*)src)[idx];
        bf16 h0 = __float2bfloat16(v.x), h1 = __float2bfloat16(v.y);
        bf16 h2 = __float2bfloat16(v.z), h3 = __float2bfloat16(v.w);
        bf16 l0 = __float2bfloat16(v.x - __bfloat162float(h0));
        bf16 l1 = __float2bfloat16(v.y - __bfloat162float(h1));
        bf16 l2 = __float2bfloat16(v.z - __bfloat162float(h2));
        bf16 l3 = __float2bfloat16(v.w - __bfloat162float(h3));
        __nv_bfloat162 a, b;
        a.x = h0; a.y = h1; b.x = h2; b.y = h3;
        ((__nv_bfloat162*)hi)[idx * 2]     = a;
        ((__nv_bfloat162*)hi)[idx * 2 + 1] = b;
        a.x = l0; a.y = l1; b.x = l2; b.y = l3;
        ((__nv_bfloat162*)lo)[idx * 2]     = a;
        ((__nv_bfloat162*)lo)[idx * 2 + 1] = b;
    }
}

// ---------------------------------------------------------------------------
// context [B,S,D] fp32 -> transposed bf16 splits [B,D,S]
// ---------------------------------------------------------------------------
__global__ __launch_bounds__(256)
void transpose_split_kernel(const float* __restrict__ ctx,
                            bf16* __restrict__ Thi, bf16* __restrict__ Tlo)
{
    __shared__ float tile[32][33];
    const int b = blockIdx.z;
    const int s0 = blockIdx.x * 32, d0 = blockIdx.y * 32;
    const int tx = threadIdx.x & 31, ty = threadIdx.x >> 5;  // 32 x 8
    const float* src = ctx + (LL)b * 1048576;
#pragma unroll
    for (int k = 0; k < 32; k += 8)
        tile[ty + k][tx] = src[(LL)(s0 + ty + k) * 1024 + d0 + tx];
    __syncthreads();
    bf16* dh = Thi + (LL)b * 1048576;
    bf16* dl = Tlo + (LL)b * 1048576;
#pragma unroll
    for (int k = 0; k < 32; k += 8) {
        float v = tile[tx][ty + k];
        bf16 h = __float2bfloat16(v);
        LL o = (LL)(d0 + ty + k) * 1024 + s0 + tx;
        dh[o] = h;
        dl[o] = __float2bfloat16(v - __bfloat162float(h));
    }
}

// ---------------------------------------------------------------------------
// Softmax over S=1024 per (b,t); probs -> d_out [T,B,S] and split [B*T,S]
// ---------------------------------------------------------------------------
__device__ __forceinline__ float warpMax(float v) {
#pragma unroll
    for (int o = 16; o; o >>= 1) v = fmaxf(v, __shfl_xor_sync(0xffffffffu, v, o));
    return v;
}
__device__ __forceinline__ float warpSum(float v) {
#pragma unroll
    for (int o = 16; o; o >>= 1) v += __shfl_xor_sync(0xffffffffu, v, o);
    return v;
}

__global__ __launch_bounds__(256)
void softmax_kernel(const float* __restrict__ scores, float* __restrict__ out,
                    bf16* __restrict__ phi, bf16* __restrict__ plo)
{
    const int bt = blockIdx.x;
    const int b = bt >> 10, t = bt & 1023;
    const float* row = scores + (LL)bt * 1024;
    float* orow = out + ((LL)t * 32 + b) * 1024;
    bf16* hrow = phi + (LL)bt * 1024;
    bf16* lrow = plo + (LL)bt * 1024;
    const int tid = threadIdx.x;

    __shared__ float shm[8], shs[8];

    float v[4];
    float mx = -1e30f;
#pragma unroll
    for (int i = 0; i < 4; ++i) { v[i] = row[tid + i * 256]; mx = fmaxf(mx, v[i]); }
    float wm = warpMax(mx);
    if ((tid & 31) == 0) shm[tid >> 5] = wm;
    __syncthreads();
    float m = shm[0];
#pragma unroll
    for (int i = 1; i < 8; ++i) m = fmaxf(m, shm[i]);

    float s = 0.f;
#pragma unroll
    for (int i = 0; i < 4; ++i) { v[i] = __expf(v[i] - m); s += v[i]; }
    float ws = warpSum(s);
    if ((tid & 31) == 0) shs[tid >> 5] = ws;
    __syncthreads();
    float tot = 0.f;
#pragma unroll
    for (int i = 0; i < 8; ++i) tot += shs[i];
    const float inv = 1.f / tot;

#pragma unroll
    for (int i = 0; i < 4; ++i) {
        float pv = v[i] * inv;
        int c = tid + i * 256;
        orow[c] = pv;
        bf16 h = __float2bfloat16(pv);
        hrow[c] = h;
        lrow[c] = __float2bfloat16(pv - __bfloat162float(h));
    }
}

// ---------------------------------------------------------------------------
// Launch
// ---------------------------------------------------------------------------
extern "C" void kernel_launch(void* const* d_in, const int* in_sizes, int n_in,
                              void* d_out, int out_size)
{
    const float* input   = (const float*)d_in[0];  // [B,T,D]
    const float* context = (const float*)d_in[1];  // [B,S,D]
    const float* W_in    = (const float*)d_in[2];  // [D,D]
    const float* W_out   = (const float*)d_in[3];  // [D,2D]

    float* out       = (float*)d_out;
    float* out_attn  = out;                                // [T,B,D]
    float* out_align = out + (LL)1024 * 32 * 1024;         // [T,B,S]

    bf16 *in_hi, *in_lo, *ctx_hi, *ctx_lo, *ctT_hi, *ctT_lo;
    bf16 *ht_hi, *ht_lo, *p_hi, *p_lo, *c_hi, *c_lo;
    bf16 *win_hi, *win_lo, *wo_hi, *wo_lo;
    float* sc;
    cudaGetSymbolAddress((void**)&in_hi,  g_in_hi);  cudaGetSymbolAddress((void**)&in_lo,  g_in_lo);
    cudaGetSymbolAddress((void**)&ctx_hi, g_ctx_hi); cudaGetSymbolAddress((void**)&ctx_lo, g_ctx_lo);
    cudaGetSymbolAddress((void**)&ctT_hi, g_ctT_hi); cudaGetSymbolAddress((void**)&ctT_lo, g_ctT_lo);
    cudaGetSymbolAddress((void**)&ht_hi,  g_ht_hi);  cudaGetSymbolAddress((void**)&ht_lo,  g_ht_lo);
    cudaGetSymbolAddress((void**)&p_hi,   g_p_hi);   cudaGetSymbolAddress((void**)&p_lo,   g_p_lo);
    cudaGetSymbolAddress((void**)&c_hi,   g_c_hi);   cudaGetSymbolAddress((void**)&c_lo,   g_c_lo);
    cudaGetSymbolAddress((void**)&win_hi, g_win_hi); cudaGetSymbolAddress((void**)&win_lo, g_win_lo);
    cudaGetSymbolAddress((void**)&wo_hi,  g_wo_hi);  cudaGetSymbolAddress((void**)&wo_lo,  g_wo_lo);
    cudaGetSymbolAddress((void**)&sc, g_sc);

    const LL M1 = 1048576;  // 1024*1024
    dim3 thr(256);

    // --- prep: splits (float4 path) ---
    split_kernel<<<32768, thr>>>(input,   in_hi,  in_lo,  8388608);
    split_kernel<<<32768, thr>>>(context, ctx_hi, ctx_lo, 8388608);
    split_kernel<<<1024,  thr>>>(W_in,    win_hi, win_lo, 262144);
    split_kernel<<<2048,  thr>>>(W_out,   wo_hi,  wo_lo,  524288);
    transpose_split_kernel<<<dim3(32, 32, 32), thr>>>(context, ctT_hi, ctT_lo);

    // --- 1. h_t = input @ W_in^T  (M=32768, N=1024) -> split ht ---
    mma_nt<1><<<dim3(8, 256, 1), thr>>>(
        in_hi, in_lo, 1024, 0,
        win_hi, win_lo, 1024, 0,
        nullptr, nullptr, 0, 0, nullptr, nullptr, 0, 0,
        nullptr, ht_hi, ht_lo, 1024, 0,
        1024, 1);

    // --- 2. align[b] = h_t[b] @ context[b]^T -> fp32 scores ---
    mma_nt<0><<<dim3(8, 8, 32), thr>>>(
        ht_hi, ht_lo, 1024, M1,
        ctx_hi, ctx_lo, 1024, M1,
        nullptr, nullptr, 0, 0, nullptr, nullptr, 0, 0,
        sc, nullptr, nullptr, 1024, M1,
        1024, 1);

    // --- 3. softmax -> d_out[T,B,S] + split probs ---
    softmax_kernel<<<32 * 1024, thr>>>(sc, out_align, p_hi, p_lo);

    // --- 4. c[b] = probs[b] @ (context[b]^T)^T -> split c ---
    mma_nt<1><<<dim3(8, 8, 32), thr>>>(
        p_hi, p_lo, 1024, M1,
        ctT_hi, ctT_lo, 1024, M1,
        nullptr, nullptr, 0, 0, nullptr, nullptr, 0, 0,
        nullptr, c_hi, c_lo, 1024, M1,
        1024, 1);

    // --- 5. attn = tanh([c, input] @ W_out^T) -> d_out[T,B,D] ---
    mma_nt<2><<<dim3(8, 8, 32), thr>>>(
        c_hi, c_lo, 1024, M1,
        wo_hi, wo_lo, 2048, 0,
        in_hi, in_lo, 1024, M1,
        wo_hi + 1024, wo_lo + 1024, 2048, 0,
        out_attn, nullptr, nullptr, 32768, 1024,
        1024, 2);

    (void)in_sizes; (void)n_in; (void)out_size;
}

// round 13
// speedup vs baseline: 1.1327x; 1.1327x over previous
#include <cuda_runtime.h>
#include <cuda_bf16.h>
#include <math.h>
#include <stdint.h>

typedef long long LL;
typedef __nv_bfloat16 bf16;

// ---------------------------------------------------------------------------
// GlobalAttention (Luong general), B=32, T=S=D=1024, fp32 in/out.
// mma.sync (HMMA) bf16 split-GEMM: 3-product hi/lo emulation of fp32.
// R11 baseline: 3765us, rel_err 4e-5. This round: BK=64 chunks (dynamic smem),
// merged split prep.
// ---------------------------------------------------------------------------

// ---- scratch (__device__ globals: allocation is forbidden) ----
__device__ bf16 g_in_hi[33554432],  g_in_lo[33554432];   // input  [B*T, D]
__device__ bf16 g_ctx_hi[33554432], g_ctx_lo[33554432];  // context[B, S, D]
__device__ bf16 g_ctT_hi[33554432], g_ctT_lo[33554432];  // context^T [B, D, S]
__device__ bf16 g_ht_hi[33554432],  g_ht_lo[33554432];   // h_t [B*T, D]
__device__ bf16 g_p_hi[33554432],   g_p_lo[33554432];    // probs [B*T, S]
__device__ bf16 g_c_hi[33554432],   g_c_lo[33554432];    // c [B*T, D]
__device__ bf16 g_win_hi[1048576],  g_win_lo[1048576];   // W_in [D, D]
__device__ bf16 g_wo_hi[2097152],   g_wo_lo[2097152];    // W_out [D, 2D]
__device__ float g_sc[33554432];                          // raw scores [B,T,S]

// ---- low-level helpers ----
__device__ __forceinline__ uint32_t smem_u32(const void* p) {
    uint32_t a;
    asm("{ .reg .u64 t; cvta.to.shared.u64 t, %1; cvt.u32.u64 %0, t; }"
        : "=r"(a) : "l"(p));
    return a;
}
__device__ __forceinline__ void cp16(uint32_t dst, const void* src) {
    asm volatile("cp.async.cg.shared.global [%0], [%1], 16;"
                 :: "r"(dst), "l"(src) : "memory");
}
__device__ __forceinline__ void ldsm_x4(uint32_t* r, uint32_t addr) {
    asm volatile("ldmatrix.sync.aligned.m8n8.x4.shared.b16 {%0,%1,%2,%3}, [%4];"
                 : "=r"(r[0]), "=r"(r[1]), "=r"(r[2]), "=r"(r[3]) : "r"(addr));
}
__device__ __forceinline__ void ldsm_x2(uint32_t* r, uint32_t addr) {
    asm volatile("ldmatrix.sync.aligned.m8n8.x2.shared.b16 {%0,%1}, [%2];"
                 : "=r"(r[0]), "=r"(r[1]) : "r"(addr));
}
__device__ __forceinline__ void mma16816(float* c, const uint32_t* a, const uint32_t* b) {
    asm volatile(
        "mma.sync.aligned.m16n8k16.row.col.f32.bf16.bf16.f32 "
        "{%0,%1,%2,%3}, {%4,%5,%6,%7}, {%8,%9}, {%0,%1,%2,%3};"
        : "+f"(c[0]), "+f"(c[1]), "+f"(c[2]), "+f"(c[3])
        : "r"(a[0]), "r"(a[1]), "r"(a[2]), "r"(a[3]), "r"(b[0]), "r"(b[1]));
}

// BK=64: 64 k-elems per row, padded to 72 (144 B row stride).
// ldmatrix 8-row phases: quad index (r*144/16) mod 8 = {0,1,2,3,4,5,6,7} — conflict-free.
#define LDKE 72
#define TILE_ELE (128 * LDKE)              // 9216 elems = 18432 B per tile
#define SMEM_BYTES (4 * TILE_ELE * 2)      // 2 bufs x (A + B) = 73728 B

// ---------------------------------------------------------------------------
// Generic NT split-GEMM: C[128,128] tile = sum of 3 hi/lo products, nseg K-segs.
// A [M,K] k-major (ld lda), B [N,K] k-major (ld ldb). BK=64, double-buffered
// cp.async pipeline, 8 warps of 64x32, mma.m16n8k16 bf16.
// MODE 0: fp32 C.  MODE 1: split bf16 (Chi,Clo).  MODE 2: tanh -> fp32 C.
// ---------------------------------------------------------------------------
template<int MODE>
__global__ __launch_bounds__(256)
void mma_nt(const bf16* __restrict__ Ahi, const bf16* __restrict__ Alo, int lda, LL sA,
            const bf16* __restrict__ Bhi, const bf16* __restrict__ Blo, int ldb, LL sB,
            const bf16* __restrict__ A2hi, const bf16* __restrict__ A2lo, int lda2, LL sA2,
            const bf16* __restrict__ B2hi, const bf16* __restrict__ B2lo, int ldb2, LL sB2,
            float* __restrict__ C, bf16* __restrict__ Chi, bf16* __restrict__ Clo,
            int ldc, LL sC, int K, int nseg)
{
    extern __shared__ __align__(16) bf16 smdyn[];
    // layout: A buf0 | A buf1 | B buf0 | B buf1, each TILE_ELE bf16

    const int tid = threadIdx.x;
    const int wid = tid >> 5, lane = tid & 31;
    const int warp_m = wid >> 2;         // 0..1
    const int warp_n = wid & 3;          // 0..3
    const int bz = blockIdx.z;
    const int rowBase = blockIdx.y * 128;
    const int colBase = blockIdx.x * 128;

    const uint32_t baseA0 = smem_u32(smdyn);
    const uint32_t baseB0 = baseA0 + 2u * TILE_ELE * 2;

    float acc[4][4][4];
#pragma unroll
    for (int mt = 0; mt < 4; ++mt)
#pragma unroll
        for (int nt = 0; nt < 4; ++nt)
#pragma unroll
            for (int k = 0; k < 4; ++k) acc[mt][nt][k] = 0.f;

    const int K64 = K >> 6;
    const int nch = 3 * nseg * K64;

    // issue cp.async loads for chunk id into buffer id&1
    auto load_chunk = [&](int id) {
        const int p = id / (nseg * K64);
        const int r0 = id - p * (nseg * K64);
        const int s = r0 / K64;
        const int k0 = (r0 - s * K64) << 6;
        const bf16* pA = (s == 0) ? ((p < 2) ? Ahi : Alo) : ((p < 2) ? A2hi : A2lo);
        const bf16* pB = (s == 0) ? ((p != 1) ? Bhi : Blo) : ((p != 1) ? B2hi : B2lo);
        const int ldA = (s == 0) ? lda : lda2;
        const int ldB = (s == 0) ? ldb : ldb2;
        const LL  sAx = (s == 0) ? sA : sA2;
        const LL  sBx = (s == 0) ? sB : sB2;
        const bf16* Ap = pA + (LL)bz * sAx + (LL)rowBase * ldA + k0;
        const bf16* Bp = pB + (LL)bz * sBx + (LL)colBase * ldB + k0;
        const int buf = id & 1;
        const uint32_t dA = baseA0 + buf * (TILE_ELE * 2);
        const uint32_t dB = baseB0 + buf * (TILE_ELE * 2);
        // 128 rows x 8 x 16B blocks = 1024 cp16 per operand; 256 thr -> 4 each
#pragma unroll
        for (int j = 0; j < 4; ++j) {
            const int cid = j * 256 + tid;         // 0..1023
            const int rr = cid >> 3, kb = cid & 7; // row, 16B block
            cp16(dA + (uint32_t)(rr * LDKE + kb * 8) * 2, Ap + (LL)rr * ldA + kb * 8);
        }
#pragma unroll
        for (int j = 0; j < 4; ++j) {
            const int cid = j * 256 + tid;
            const int rr = cid >> 3, kb = cid & 7;
            cp16(dB + (uint32_t)(rr * LDKE + kb * 8) * 2, Bp + (LL)rr * ldB + kb * 8);
        }
        asm volatile("cp.async.commit_group;" ::: "memory");
    };

    load_chunk(0);

#pragma unroll 1
    for (int i = 0; i < nch; ++i) {
        if (i + 1 < nch) {
            load_chunk(i + 1);
            asm volatile("cp.async.wait_group 1;" ::: "memory");
        } else {
            asm volatile("cp.async.wait_group 0;" ::: "memory");
        }
        __syncthreads();

        const int buf = i & 1;
        const uint32_t bA = baseA0 + buf * (TILE_ELE * 2);
        const uint32_t bB = baseB0 + buf * (TILE_ELE * 2);

#pragma unroll
        for (int ks = 0; ks < 4; ++ks) {
            uint32_t af[4][4], bfr[4][2];
#pragma unroll
            for (int mt = 0; mt < 4; ++mt) {
                const int row = warp_m * 64 + mt * 16 + (lane & 15);
                ldsm_x4(af[mt], bA + (uint32_t)(row * LDKE + ks * 16 + (lane >> 4) * 8) * 2);
            }
#pragma unroll
            for (int nt = 0; nt < 4; ++nt) {
                const int row = warp_n * 32 + nt * 8 + (lane & 7);
                ldsm_x2(bfr[nt], bB + (uint32_t)(row * LDKE + ks * 16 + ((lane >> 3) & 1) * 8) * 2);
            }
#pragma unroll
            for (int mt = 0; mt < 4; ++mt)
#pragma unroll
                for (int nt = 0; nt < 4; ++nt)
                    mma16816(acc[mt][nt], af[mt], bfr[nt]);
        }
        __syncthreads();
    }

    // ---- epilogue ----
    const int rrow = rowBase + warp_m * 64 + (lane >> 2);
    const int ccol = colBase + warp_n * 32 + (lane & 3) * 2;
#pragma unroll
    for (int mt = 0; mt < 4; ++mt) {
#pragma unroll
        for (int nt = 0; nt < 4; ++nt) {
            const int r0 = rrow + mt * 16;
            const int cc = ccol + nt * 8;
            float v0 = acc[mt][nt][0], v1 = acc[mt][nt][1];
            float v2 = acc[mt][nt][2], v3 = acc[mt][nt][3];
            if (MODE == 2) {
                v0 = tanhf(v0); v1 = tanhf(v1); v2 = tanhf(v2); v3 = tanhf(v3);
            }
            if (MODE == 0 || MODE == 2) {
                float* Cr = C + (LL)bz * sC;
                *(float2*)(Cr + (LL)r0 * ldc + cc)       = make_float2(v0, v1);
                *(float2*)(Cr + (LL)(r0 + 8) * ldc + cc) = make_float2(v2, v3);
            } else {
                bf16 h0 = __float2bfloat16(v0), h1 = __float2bfloat16(v1);
                bf16 h2 = __float2bfloat16(v2), h3 = __float2bfloat16(v3);
                bf16 l0 = __float2bfloat16(v0 - __bfloat162float(h0));
                bf16 l1 = __float2bfloat16(v1 - __bfloat162float(h1));
                bf16 l2 = __float2bfloat16(v2 - __bfloat162float(h2));
                bf16 l3 = __float2bfloat16(v3 - __bfloat162float(h3));
                bf16* Hr = Chi + (LL)bz * sC;
                bf16* Lr = Clo + (LL)bz * sC;
                __nv_bfloat162 t;
                t.x = h0; t.y = h1; *(__nv_bfloat162*)(Hr + (LL)r0 * ldc + cc) = t;
                t.x = h2; t.y = h3; *(__nv_bfloat162*)(Hr + (LL)(r0 + 8) * ldc + cc) = t;
                t.x = l0; t.y = l1; *(__nv_bfloat162*)(Lr + (LL)r0 * ldc + cc) = t;
                t.x = l2; t.y = l3; *(__nv_bfloat162*)(Lr + (LL)(r0 + 8) * ldc + cc) = t;
            }
        }
    }
}

// ---------------------------------------------------------------------------
// Merged fp32 -> bf16 hi/lo split for all four inputs (one launch).
// Block ranges (in float4 units / 256-thread blocks):
//   input  : blocks [0, 32768)        (8388608 float4)
//   context: blocks [32768, 65536)    (8388608 float4)
//   W_in   : blocks [65536, 66560)    (262144 float4)
//   W_out  : blocks [66560, 68608)    (524288 float4)
// ---------------------------------------------------------------------------
__device__ __forceinline__ void split4(const float* __restrict__ src,
                                       bf16* __restrict__ hi, bf16* __restrict__ lo,
                                       int idx)
{
    float4 v = ((const float4*)src)[idx];
    bf16 h0 = __float2bfloat16(v.x), h1 = __float2bfloat16(v.y);
    bf16 h2 = __float2bfloat16(v.z), h3 = __float2bfloat16(v.w);
    bf16 l0 = __float2bfloat16(v.x - __bfloat162float(h0));
    bf16 l1 = __float2bfloat16(v.y - __bfloat162float(h1));
    bf16 l2 = __float2bfloat16(v.z - __bfloat162float(h2));
    bf16 l3 = __float2bfloat16(v.w - __bfloat162float(h3));
    __nv_bfloat162 a, b;
    a.x = h0; a.y = h1; b.x = h2; b.y = h3;
    ((__nv_bfloat162*)hi)[idx * 2]     = a;
    ((__nv_bfloat162*)hi)[idx * 2 + 1] = b;
    a.x = l0; a.y = l1; b.x = l2; b.y = l3;
    ((__nv_bfloat162*)lo)[idx * 2]     = a;
    ((__nv_bfloat162*)lo)[idx * 2 + 1] = b;
}

__global__ __launch_bounds__(256)
void split_all_kernel(const float* __restrict__ input, const float* __restrict__ context,
                      const float* __restrict__ W_in, const float* __restrict__ W_out,
                      bf16* in_hi, bf16* in_lo, bf16* ctx_hi, bf16* ctx_lo,
                      bf16* win_hi, bf16* win_lo, bf16* wo_hi, bf16* wo_lo)
{
    const int blk = blockIdx.x;
    if (blk < 32768) {
        split4(input, in_hi, in_lo, blk * 256 + threadIdx.x);
    } else if (blk < 65536) {
        split4(context, ctx_hi, ctx_lo, (blk - 32768) * 256 + threadIdx.x);
    } else if (blk < 66560) {
        split4(W_in, win_hi, win_lo, (blk - 65536) * 256 + threadIdx.x);
    } else {
        split4(W_out, wo_hi, wo_lo, (blk - 66560) * 256 + threadIdx.x);
    }
}

// ---------------------------------------------------------------------------
// context [B,S,D] fp32 -> transposed bf16 splits [B,D,S]
// ---------------------------------------------------------------------------
__global__ __launch_bounds__(256)
void transpose_split_kernel(const float* __restrict__ ctx,
                            bf16* __restrict__ Thi, bf16* __restrict__ Tlo)
{
    __shared__ float tile[32][33];
    const int b = blockIdx.z;
    const int s0 = blockIdx.x * 32, d0 = blockIdx.y * 32;
    const int tx = threadIdx.x & 31, ty = threadIdx.x >> 5;  // 32 x 8
    const float* src = ctx + (LL)b * 1048576;
#pragma unroll
    for (int k = 0; k < 32; k += 8)
        tile[ty + k][tx] = src[(LL)(s0 + ty + k) * 1024 + d0 + tx];
    __syncthreads();
    bf16* dh = Thi + (LL)b * 1048576;
    bf16* dl = Tlo + (LL)b * 1048576;
#pragma unroll
    for (int k = 0; k < 32; k += 8) {
        float v = tile[tx][ty + k];
        bf16 h = __float2bfloat16(v);
        LL o = (LL)(d0 + ty + k) * 1024 + s0 + tx;
        dh[o] = h;
        dl[o] = __float2bfloat16(v - __bfloat162float(h));
    }
}

// ---------------------------------------------------------------------------
// Softmax over S=1024 per (b,t); probs -> d_out [T,B,S] and split [B*T,S]
// ---------------------------------------------------------------------------
__device__ __forceinline__ float warpMax(float v) {
#pragma unroll
    for (int o = 16; o; o >>= 1) v = fmaxf(v, __shfl_xor_sync(0xffffffffu, v, o));
    return v;
}
__device__ __forceinline__ float warpSum(float v) {
#pragma unroll
    for (int o = 16; o; o >>= 1) v += __shfl_xor_sync(0xffffffffu, v, o);
    return v;
}

__global__ __launch_bounds__(256)
void softmax_kernel(const float* __restrict__ scores, float* __restrict__ out,
                    bf16* __restrict__ phi, bf16* __restrict__ plo)
{
    const int bt = blockIdx.x;
    const int b = bt >> 10, t = bt & 1023;
    const float* row = scores + (LL)bt * 1024;
    float* orow = out + ((LL)t * 32 + b) * 1024;
    bf16* hrow = phi + (LL)bt * 1024;
    bf16* lrow = plo + (LL)bt * 1024;
    const int tid = threadIdx.x;

    __shared__ float shm[8], shs[8];

    float v[4];
    float mx = -1e30f;
#pragma unroll
    for (int i = 0; i < 4; ++i) { v[i] = row[tid + i * 256]; mx = fmaxf(mx, v[i]); }
    float wm = warpMax(mx);
    if ((tid & 31) == 0) shm[tid >> 5] = wm;
    __syncthreads();
    float m = shm[0];
#pragma unroll
    for (int i = 1; i < 8; ++i) m = fmaxf(m, shm[i]);

    float s = 0.f;
#pragma unroll
    for (int i = 0; i < 4; ++i) { v[i] = __expf(v[i] - m); s += v[i]; }
    float ws = warpSum(s);
    if ((tid & 31) == 0) shs[tid >> 5] = ws;
    __syncthreads();
    float tot = 0.f;
#pragma unroll
    for (int i = 0; i < 8; ++i) tot += shs[i];
    const float inv = 1.f / tot;

#pragma unroll
    for (int i = 0; i < 4; ++i) {
        float pv = v[i] * inv;
        int c = tid + i * 256;
        orow[c] = pv;
        bf16 h = __float2bfloat16(pv);
        hrow[c] = h;
        lrow[c] = __float2bfloat16(pv - __bfloat162float(h));
    }
}

// ---------------------------------------------------------------------------
// Launch
// ---------------------------------------------------------------------------
extern "C" void kernel_launch(void* const* d_in, const int* in_sizes, int n_in,
                              void* d_out, int out_size)
{
    const float* input   = (const float*)d_in[0];  // [B,T,D]
    const float* context = (const float*)d_in[1];  // [B,S,D]
    const float* W_in    = (const float*)d_in[2];  // [D,D]
    const float* W_out   = (const float*)d_in[3];  // [D,2D]

    float* out       = (float*)d_out;
    float* out_attn  = out;                                // [T,B,D]
    float* out_align = out + (LL)1024 * 32 * 1024;         // [T,B,S]

    bf16 *in_hi, *in_lo, *ctx_hi, *ctx_lo, *ctT_hi, *ctT_lo;
    bf16 *ht_hi, *ht_lo, *p_hi, *p_lo, *c_hi, *c_lo;
    bf16 *win_hi, *win_lo, *wo_hi, *wo_lo;
    float* sc;
    cudaGetSymbolAddress((void**)&in_hi,  g_in_hi);  cudaGetSymbolAddress((void**)&in_lo,  g_in_lo);
    cudaGetSymbolAddress((void**)&ctx_hi, g_ctx_hi); cudaGetSymbolAddress((void**)&ctx_lo, g_ctx_lo);
    cudaGetSymbolAddress((void**)&ctT_hi, g_ctT_hi); cudaGetSymbolAddress((void**)&ctT_lo, g_ctT_lo);
    cudaGetSymbolAddress((void**)&ht_hi,  g_ht_hi);  cudaGetSymbolAddress((void**)&ht_lo,  g_ht_lo);
    cudaGetSymbolAddress((void**)&p_hi,   g_p_hi);   cudaGetSymbolAddress((void**)&p_lo,   g_p_lo);
    cudaGetSymbolAddress((void**)&c_hi,   g_c_hi);   cudaGetSymbolAddress((void**)&c_lo,   g_c_lo);
    cudaGetSymbolAddress((void**)&win_hi, g_win_hi); cudaGetSymbolAddress((void**)&win_lo, g_win_lo);
    cudaGetSymbolAddress((void**)&wo_hi,  g_wo_hi);  cudaGetSymbolAddress((void**)&wo_lo,  g_wo_lo);
    cudaGetSymbolAddress((void**)&sc, g_sc);

    cudaFuncSetAttribute(mma_nt<0>, cudaFuncAttributeMaxDynamicSharedMemorySize, SMEM_BYTES);
    cudaFuncSetAttribute(mma_nt<1>, cudaFuncAttributeMaxDynamicSharedMemorySize, SMEM_BYTES);
    cudaFuncSetAttribute(mma_nt<2>, cudaFuncAttributeMaxDynamicSharedMemorySize, SMEM_BYTES);

    const LL M1 = 1048576;  // 1024*1024
    dim3 thr(256);

    // --- prep: merged splits (1 launch) + transpose split ---
    split_all_kernel<<<68608, thr>>>(input, context, W_in, W_out,
                                     in_hi, in_lo, ctx_hi, ctx_lo,
                                     win_hi, win_lo, wo_hi, wo_lo);
    transpose_split_kernel<<<dim3(32, 32, 32), thr>>>(context, ctT_hi, ctT_lo);

    // --- 1. h_t = input @ W_in^T  (M=32768, N=1024) -> split ht ---
    mma_nt<1><<<dim3(8, 256, 1), thr, SMEM_BYTES>>>(
        in_hi, in_lo, 1024, 0,
        win_hi, win_lo, 1024, 0,
        nullptr, nullptr, 0, 0, nullptr, nullptr, 0, 0,
        nullptr, ht_hi, ht_lo, 1024, 0,
        1024, 1);

    // --- 2. align[b] = h_t[b] @ context[b]^T -> fp32 scores ---
    mma_nt<0><<<dim3(8, 8, 32), thr, SMEM_BYTES>>>(
        ht_hi, ht_lo, 1024, M1,
        ctx_hi, ctx_lo, 1024, M1,
        nullptr, nullptr, 0, 0, nullptr, nullptr, 0, 0,
        sc, nullptr, nullptr, 1024, M1,
        1024, 1);

    // --- 3. softmax -> d_out[T,B,S] + split probs ---
    softmax_kernel<<<32 * 1024, thr>>>(sc, out_align, p_hi, p_lo);

    // --- 4. c[b] = probs[b] @ (context[b]^T)^T -> split c ---
    mma_nt<1><<<dim3(8, 8, 32), thr, SMEM_BYTES>>>(
        p_hi, p_lo, 1024, M1,
        ctT_hi, ctT_lo, 1024, M1,
        nullptr, nullptr, 0, 0, nullptr, nullptr, 0, 0,
        nullptr, c_hi, c_lo, 1024, M1,
        1024, 1);

    // --- 5. attn = tanh([c, input] @ W_out^T) -> d_out[T,B,D] ---
    mma_nt<2><<<dim3(8, 8, 32), thr, SMEM_BYTES>>>(
        c_hi, c_lo, 1024, M1,
        wo_hi, wo_lo, 2048, 0,
        in_hi, in_lo, 1024, M1,
        wo_hi + 1024, wo_lo + 1024, 2048, 0,
        out_attn, nullptr, nullptr, 32768, 1024,
        1024, 2);

    (void)in_sizes; (void)n_in; (void)out_size;
}

// round 14
// speedup vs baseline: 1.2622x; 1.1143x over previous
#include <cuda_runtime.h>
#include <cuda_bf16.h>
#include <math.h>
#include <stdint.h>

typedef long long LL;
typedef __nv_bfloat16 bf16;

// ---------------------------------------------------------------------------
// GlobalAttention (Luong general), B=32, T=S=D=1024, fp32 in/out.
// mma.sync bf16 split-GEMM, FUSED 3-product chunks (hi*hi + hi*lo + lo*hi
// computed per k-chunk from one tile load of Ahi/Alo/Bhi/Blo).
// R13 baseline: 3324us (tensor 54.9%, L1 45%). This round: product fusion.
// ---------------------------------------------------------------------------

// ---- scratch (__device__ globals: allocation is forbidden) ----
__device__ bf16 g_in_hi[33554432],  g_in_lo[33554432];   // input  [B*T, D]
__device__ bf16 g_ctx_hi[33554432], g_ctx_lo[33554432];  // context[B, S, D]
__device__ bf16 g_ctT_hi[33554432], g_ctT_lo[33554432];  // context^T [B, D, S]
__device__ bf16 g_ht_hi[33554432],  g_ht_lo[33554432];   // h_t [B*T, D]
__device__ bf16 g_p_hi[33554432],   g_p_lo[33554432];    // probs [B*T, S]
__device__ bf16 g_c_hi[33554432],   g_c_lo[33554432];    // c [B*T, D]
__device__ bf16 g_win_hi[1048576],  g_win_lo[1048576];   // W_in [D, D]
__device__ bf16 g_wo_hi[2097152],   g_wo_lo[2097152];    // W_out [D, 2D]
__device__ float g_sc[33554432];                          // raw scores [B,T,S]

// ---- low-level helpers ----
__device__ __forceinline__ uint32_t smem_u32(const void* p) {
    uint32_t a;
    asm("{ .reg .u64 t; cvta.to.shared.u64 t, %1; cvt.u32.u64 %0, t; }"
        : "=r"(a) : "l"(p));
    return a;
}
__device__ __forceinline__ void cp16(uint32_t dst, const void* src) {
    asm volatile("cp.async.cg.shared.global [%0], [%1], 16;"
                 :: "r"(dst), "l"(src) : "memory");
}
__device__ __forceinline__ void ldsm_x4(uint32_t* r, uint32_t addr) {
    asm volatile("ldmatrix.sync.aligned.m8n8.x4.shared.b16 {%0,%1,%2,%3}, [%4];"
                 : "=r"(r[0]), "=r"(r[1]), "=r"(r[2]), "=r"(r[3]) : "r"(addr));
}
__device__ __forceinline__ void ldsm_x2(uint32_t* r, uint32_t addr) {
    asm volatile("ldmatrix.sync.aligned.m8n8.x2.shared.b16 {%0,%1}, [%2];"
                 : "=r"(r[0]), "=r"(r[1]) : "r"(addr));
}
__device__ __forceinline__ void mma16816(float* c, const uint32_t* a, const uint32_t* b) {
    asm volatile(
        "mma.sync.aligned.m16n8k16.row.col.f32.bf16.bf16.f32 "
        "{%0,%1,%2,%3}, {%4,%5,%6,%7}, {%8,%9}, {%0,%1,%2,%3};"
        : "+f"(c[0]), "+f"(c[1]), "+f"(c[2]), "+f"(c[3])
        : "r"(a[0]), "r"(a[1]), "r"(a[2]), "r"(a[3]), "r"(b[0]), "r"(b[1]));
}

// BK=32, rows padded to 40 elems (80 B) — R11-verified conflict-free layout.
#define LDKE 40
#define TILE_ELE (128 * LDKE)               // 5120 elems = 10240 B per tile
#define TILE_B   (TILE_ELE * 2)             // bytes
// smem: Ahi[2] | Alo[2] | Bhi[2] | Blo[2]  (double buffered)
#define SMEM_BYTES (8 * TILE_B)             // 81920 B

// ---------------------------------------------------------------------------
// Fused NT split-GEMM: per chunk load Ahi/Alo/Bhi/Blo, compute
// hi*hi + hi*lo + lo*hi. nseg K-segments. 8 warps of 64x32, m16n8k16.
// MODE 0: fp32 C.  MODE 1: split bf16 (Chi,Clo).  MODE 2: tanh -> fp32 C.
// ---------------------------------------------------------------------------
template<int MODE>
__global__ __launch_bounds__(256, 2)
void mma_nt(const bf16* __restrict__ Ahi, const bf16* __restrict__ Alo, int lda, LL sA,
            const bf16* __restrict__ Bhi, const bf16* __restrict__ Blo, int ldb, LL sB,
            const bf16* __restrict__ A2hi, const bf16* __restrict__ A2lo, int lda2, LL sA2,
            const bf16* __restrict__ B2hi, const bf16* __restrict__ B2lo, int ldb2, LL sB2,
            float* __restrict__ C, bf16* __restrict__ Chi, bf16* __restrict__ Clo,
            int ldc, LL sC, int K, int nseg)
{
    extern __shared__ __align__(16) bf16 smdyn[];

    const int tid = threadIdx.x;
    const int wid = tid >> 5, lane = tid & 31;
    const int warp_m = wid >> 2;         // 0..1
    const int warp_n = wid & 3;          // 0..3
    const int bz = blockIdx.z;
    const int rowBase = blockIdx.y * 128;
    const int colBase = blockIdx.x * 128;

    const uint32_t base   = smem_u32(smdyn);
    const uint32_t bAhi0 = base;
    const uint32_t bAlo0 = base + 2u * TILE_B;
    const uint32_t bBhi0 = base + 4u * TILE_B;
    const uint32_t bBlo0 = base + 6u * TILE_B;

    float acc[4][4][4];
#pragma unroll
    for (int mt = 0; mt < 4; ++mt)
#pragma unroll
        for (int nt = 0; nt < 4; ++nt)
#pragma unroll
            for (int k = 0; k < 4; ++k) acc[mt][nt][k] = 0.f;

    const int K32 = K >> 5;
    const int nch = nseg * K32;

    // issue cp.async loads for chunk id into buffer id&1 (4 tiles)
    auto load_chunk = [&](int id) {
        const int s  = id / K32;
        const int k0 = (id - s * K32) << 5;
        const bf16* pAh = (s == 0) ? Ahi : A2hi;
        const bf16* pAl = (s == 0) ? Alo : A2lo;
        const bf16* pBh = (s == 0) ? Bhi : B2hi;
        const bf16* pBl = (s == 0) ? Blo : B2lo;
        const int ldA = (s == 0) ? lda : lda2;
        const int ldB = (s == 0) ? ldb : ldb2;
        const LL  sAx = (s == 0) ? sA : sA2;
        const LL  sBx = (s == 0) ? sB : sB2;
        const LL  offA = (LL)bz * sAx + (LL)rowBase * ldA + k0;
        const LL  offB = (LL)bz * sBx + (LL)colBase * ldB + k0;
        const int buf = id & 1;
        const uint32_t dAh = bAhi0 + buf * TILE_B;
        const uint32_t dAl = bAlo0 + buf * TILE_B;
        const uint32_t dBh = bBhi0 + buf * TILE_B;
        const uint32_t dBl = bBlo0 + buf * TILE_B;
        // each tile: 128 rows x 4 x 16B blocks = 512 cp16; 256 thr -> 2 each
#pragma unroll
        for (int j = 0; j < 2; ++j) {
            const int cid = j * 256 + tid;          // 0..511
            const int rr = cid >> 2, kb = cid & 3;  // row, 16B block
            const uint32_t so = (uint32_t)(rr * LDKE + kb * 8) * 2;
            cp16(dAh + so, pAh + offA + (LL)rr * ldA + kb * 8);
            cp16(dAl + so, pAl + offA + (LL)rr * ldA + kb * 8);
        }
#pragma unroll
        for (int j = 0; j < 2; ++j) {
            const int cid = j * 256 + tid;
            const int rr = cid >> 2, kb = cid & 3;
            const uint32_t so = (uint32_t)(rr * LDKE + kb * 8) * 2;
            cp16(dBh + so, pBh + offB + (LL)rr * ldB + kb * 8);
            cp16(dBl + so, pBl + offB + (LL)rr * ldB + kb * 8);
        }
        asm volatile("cp.async.commit_group;" ::: "memory");
    };

    load_chunk(0);

#pragma unroll 1
    for (int i = 0; i < nch; ++i) {
        if (i + 1 < nch) {
            load_chunk(i + 1);
            asm volatile("cp.async.wait_group 1;" ::: "memory");
        } else {
            asm volatile("cp.async.wait_group 0;" ::: "memory");
        }
        __syncthreads();

        const int buf = i & 1;
        const uint32_t tAh = bAhi0 + buf * TILE_B;
        const uint32_t tAl = bAlo0 + buf * TILE_B;
        const uint32_t tBh = bBhi0 + buf * TILE_B;
        const uint32_t tBl = bBlo0 + buf * TILE_B;

#pragma unroll
        for (int ks = 0; ks < 2; ++ks) {
            const uint32_t aoff = (uint32_t)(ks * 16 + (lane >> 4) * 8) * 2;
            const uint32_t boff = (uint32_t)(ks * 16 + ((lane >> 3) & 1) * 8) * 2;

            uint32_t ah[4][4], bh[4][2];
#pragma unroll
            for (int mt = 0; mt < 4; ++mt) {
                const int row = warp_m * 64 + mt * 16 + (lane & 15);
                ldsm_x4(ah[mt], tAh + (uint32_t)(row * LDKE) * 2 + aoff);
            }
#pragma unroll
            for (int nt = 0; nt < 4; ++nt) {
                const int row = warp_n * 32 + nt * 8 + (lane & 7);
                ldsm_x2(bh[nt], tBh + (uint32_t)(row * LDKE) * 2 + boff);
            }
            // hi * hi
#pragma unroll
            for (int mt = 0; mt < 4; ++mt)
#pragma unroll
                for (int nt = 0; nt < 4; ++nt)
                    mma16816(acc[mt][nt], ah[mt], bh[nt]);

            // hi * lo
            {
                uint32_t bl[4][2];
#pragma unroll
                for (int nt = 0; nt < 4; ++nt) {
                    const int row = warp_n * 32 + nt * 8 + (lane & 7);
                    ldsm_x2(bl[nt], tBl + (uint32_t)(row * LDKE) * 2 + boff);
                }
#pragma unroll
                for (int mt = 0; mt < 4; ++mt)
#pragma unroll
                    for (int nt = 0; nt < 4; ++nt)
                        mma16816(acc[mt][nt], ah[mt], bl[nt]);
            }

            // lo * hi  (A-hi fragments dead; compiler can reuse their regs)
            {
                uint32_t al[4][4];
#pragma unroll
                for (int mt = 0; mt < 4; ++mt) {
                    const int row = warp_m * 64 + mt * 16 + (lane & 15);
                    ldsm_x4(al[mt], tAl + (uint32_t)(row * LDKE) * 2 + aoff);
                }
#pragma unroll
                for (int mt = 0; mt < 4; ++mt)
#pragma unroll
                    for (int nt = 0; nt < 4; ++nt)
                        mma16816(acc[mt][nt], al[mt], bh[nt]);
            }
        }
        __syncthreads();
    }

    // ---- epilogue ----
    const int rrow = rowBase + warp_m * 64 + (lane >> 2);
    const int ccol = colBase + warp_n * 32 + (lane & 3) * 2;
#pragma unroll
    for (int mt = 0; mt < 4; ++mt) {
#pragma unroll
        for (int nt = 0; nt < 4; ++nt) {
            const int r0 = rrow + mt * 16;
            const int cc = ccol + nt * 8;
            float v0 = acc[mt][nt][0], v1 = acc[mt][nt][1];
            float v2 = acc[mt][nt][2], v3 = acc[mt][nt][3];
            if (MODE == 2) {
                v0 = tanhf(v0); v1 = tanhf(v1); v2 = tanhf(v2); v3 = tanhf(v3);
            }
            if (MODE == 0 || MODE == 2) {
                float* Cr = C + (LL)bz * sC;
                *(float2*)(Cr + (LL)r0 * ldc + cc)       = make_float2(v0, v1);
                *(float2*)(Cr + (LL)(r0 + 8) * ldc + cc) = make_float2(v2, v3);
            } else {
                bf16 h0 = __float2bfloat16(v0), h1 = __float2bfloat16(v1);
                bf16 h2 = __float2bfloat16(v2), h3 = __float2bfloat16(v3);
                bf16 l0 = __float2bfloat16(v0 - __bfloat162float(h0));
                bf16 l1 = __float2bfloat16(v1 - __bfloat162float(h1));
                bf16 l2 = __float2bfloat16(v2 - __bfloat162float(h2));
                bf16 l3 = __float2bfloat16(v3 - __bfloat162float(h3));
                bf16* Hr = Chi + (LL)bz * sC;
                bf16* Lr = Clo + (LL)bz * sC;
                __nv_bfloat162 t;
                t.x = h0; t.y = h1; *(__nv_bfloat162*)(Hr + (LL)r0 * ldc + cc) = t;
                t.x = h2; t.y = h3; *(__nv_bfloat162*)(Hr + (LL)(r0 + 8) * ldc + cc) = t;
                t.x = l0; t.y = l1; *(__nv_bfloat162*)(Lr + (LL)r0 * ldc + cc) = t;
                t.x = l2; t.y = l3; *(__nv_bfloat162*)(Lr + (LL)(r0 + 8) * ldc + cc) = t;
            }
        }
    }
}

// ---------------------------------------------------------------------------
// Merged fp32 -> bf16 hi/lo split for all four inputs (one launch).
// ---------------------------------------------------------------------------
__device__ __forceinline__ void split4(const float* __restrict__ src,
                                       bf16* __restrict__ hi, bf16* __restrict__ lo,
                                       int idx)
{
    float4 v = ((const float4*)src)[idx];
    bf16 h0 = __float2bfloat16(v.x), h1 = __float2bfloat16(v.y);
    bf16 h2 = __float2bfloat16(v.z), h3 = __float2bfloat16(v.w);
    bf16 l0 = __float2bfloat16(v.x - __bfloat162float(h0));
    bf16 l1 = __float2bfloat16(v.y - __bfloat162float(h1));
    bf16 l2 = __float2bfloat16(v.z - __bfloat162float(h2));
    bf16 l3 = __float2bfloat16(v.w - __bfloat162float(h3));
    __nv_bfloat162 a, b;
    a.x = h0; a.y = h1; b.x = h2; b.y = h3;
    ((__nv_bfloat162*)hi)[idx * 2]     = a;
    ((__nv_bfloat162*)hi)[idx * 2 + 1] = b;
    a.x = l0; a.y = l1; b.x = l2; b.y = l3;
    ((__nv_bfloat162*)lo)[idx * 2]     = a;
    ((__nv_bfloat162*)lo)[idx * 2 + 1] = b;
}

__global__ __launch_bounds__(256)
void split_all_kernel(const float* __restrict__ input, const float* __restrict__ context,
                      const float* __restrict__ W_in, const float* __restrict__ W_out,
                      bf16* in_hi, bf16* in_lo, bf16* ctx_hi, bf16* ctx_lo,
                      bf16* win_hi, bf16* win_lo, bf16* wo_hi, bf16* wo_lo)
{
    const int blk = blockIdx.x;
    if (blk < 32768) {
        split4(input, in_hi, in_lo, blk * 256 + threadIdx.x);
    } else if (blk < 65536) {
        split4(context, ctx_hi, ctx_lo, (blk - 32768) * 256 + threadIdx.x);
    } else if (blk < 66560) {
        split4(W_in, win_hi, win_lo, (blk - 65536) * 256 + threadIdx.x);
    } else {
        split4(W_out, wo_hi, wo_lo, (blk - 66560) * 256 + threadIdx.x);
    }
}

// ---------------------------------------------------------------------------
// context [B,S,D] fp32 -> transposed bf16 splits [B,D,S]
// ---------------------------------------------------------------------------
__global__ __launch_bounds__(256)
void transpose_split_kernel(const float* __restrict__ ctx,
                            bf16* __restrict__ Thi, bf16* __restrict__ Tlo)
{
    __shared__ float tile[32][33];
    const int b = blockIdx.z;
    const int s0 = blockIdx.x * 32, d0 = blockIdx.y * 32;
    const int tx = threadIdx.x & 31, ty = threadIdx.x >> 5;  // 32 x 8
    const float* src = ctx + (LL)b * 1048576;
#pragma unroll
    for (int k = 0; k < 32; k += 8)
        tile[ty + k][tx] = src[(LL)(s0 + ty + k) * 1024 + d0 + tx];
    __syncthreads();
    bf16* dh = Thi + (LL)b * 1048576;
    bf16* dl = Tlo + (LL)b * 1048576;
#pragma unroll
    for (int k = 0; k < 32; k += 8) {
        float v = tile[tx][ty + k];
        bf16 h = __float2bfloat16(v);
        LL o = (LL)(d0 + ty + k) * 1024 + s0 + tx;
        dh[o] = h;
        dl[o] = __float2bfloat16(v - __bfloat162float(h));
    }
}

// ---------------------------------------------------------------------------
// Softmax over S=1024 per (b,t); probs -> d_out [T,B,S] and split [B*T,S]
// ---------------------------------------------------------------------------
__device__ __forceinline__ float warpMax(float v) {
#pragma unroll
    for (int o = 16; o; o >>= 1) v = fmaxf(v, __shfl_xor_sync(0xffffffffu, v, o));
    return v;
}
__device__ __forceinline__ float warpSum(float v) {
#pragma unroll
    for (int o = 16; o; o >>= 1) v += __shfl_xor_sync(0xffffffffu, v, o);
    return v;
}

__global__ __launch_bounds__(256)
void softmax_kernel(const float* __restrict__ scores, float* __restrict__ out,
                    bf16* __restrict__ phi, bf16* __restrict__ plo)
{
    const int bt = blockIdx.x;
    const int b = bt >> 10, t = bt & 1023;
    const float* row = scores + (LL)bt * 1024;
    float* orow = out + ((LL)t * 32 + b) * 1024;
    bf16* hrow = phi + (LL)bt * 1024;
    bf16* lrow = plo + (LL)bt * 1024;
    const int tid = threadIdx.x;

    __shared__ float shm[8], shs[8];

    float v[4];
    float mx = -1e30f;
#pragma unroll
    for (int i = 0; i < 4; ++i) { v[i] = row[tid + i * 256]; mx = fmaxf(mx, v[i]); }
    float wm = warpMax(mx);
    if ((tid & 31) == 0) shm[tid >> 5] = wm;
    __syncthreads();
    float m = shm[0];
#pragma unroll
    for (int i = 1; i < 8; ++i) m = fmaxf(m, shm[i]);

    float s = 0.f;
#pragma unroll
    for (int i = 0; i < 4; ++i) { v[i] = __expf(v[i] - m); s += v[i]; }
    float ws = warpSum(s);
    if ((tid & 31) == 0) shs[tid >> 5] = ws;
    __syncthreads();
    float tot = 0.f;
#pragma unroll
    for (int i = 0; i < 8; ++i) tot += shs[i];
    const float inv = 1.f / tot;

#pragma unroll
    for (int i = 0; i < 4; ++i) {
        float pv = v[i] * inv;
        int c = tid + i * 256;
        orow[c] = pv;
        bf16 h = __float2bfloat16(pv);
        hrow[c] = h;
        lrow[c] = __float2bfloat16(pv - __bfloat162float(h));
    }
}

// ---------------------------------------------------------------------------
// Launch
// ---------------------------------------------------------------------------
extern "C" void kernel_launch(void* const* d_in, const int* in_sizes, int n_in,
                              void* d_out, int out_size)
{
    const float* input   = (const float*)d_in[0];  // [B,T,D]
    const float* context = (const float*)d_in[1];  // [B,S,D]
    const float* W_in    = (const float*)d_in[2];  // [D,D]
    const float* W_out   = (const float*)d_in[3];  // [D,2D]

    float* out       = (float*)d_out;
    float* out_attn  = out;                                // [T,B,D]
    float* out_align = out + (LL)1024 * 32 * 1024;         // [T,B,S]

    bf16 *in_hi, *in_lo, *ctx_hi, *ctx_lo, *ctT_hi, *ctT_lo;
    bf16 *ht_hi, *ht_lo, *p_hi, *p_lo, *c_hi, *c_lo;
    bf16 *win_hi, *win_lo, *wo_hi, *wo_lo;
    float* sc;
    cudaGetSymbolAddress((void**)&in_hi,  g_in_hi);  cudaGetSymbolAddress((void**)&in_lo,  g_in_lo);
    cudaGetSymbolAddress((void**)&ctx_hi, g_ctx_hi); cudaGetSymbolAddress((void**)&ctx_lo, g_ctx_lo);
    cudaGetSymbolAddress((void**)&ctT_hi, g_ctT_hi); cudaGetSymbolAddress((void**)&ctT_lo, g_ctT_lo);
    cudaGetSymbolAddress((void**)&ht_hi,  g_ht_hi);  cudaGetSymbolAddress((void**)&ht_lo,  g_ht_lo);
    cudaGetSymbolAddress((void**)&p_hi,   g_p_hi);   cudaGetSymbolAddress((void**)&p_lo,   g_p_lo);
    cudaGetSymbolAddress((void**)&c_hi,   g_c_hi);   cudaGetSymbolAddress((void**)&c_lo,   g_c_lo);
    cudaGetSymbolAddress((void**)&win_hi, g_win_hi); cudaGetSymbolAddress((void**)&win_lo, g_win_lo);
    cudaGetSymbolAddress((void**)&wo_hi,  g_wo_hi);  cudaGetSymbolAddress((void**)&wo_lo,  g_wo_lo);
    cudaGetSymbolAddress((void**)&sc, g_sc);

    cudaFuncSetAttribute(mma_nt<0>, cudaFuncAttributeMaxDynamicSharedMemorySize, SMEM_BYTES);
    cudaFuncSetAttribute(mma_nt<1>, cudaFuncAttributeMaxDynamicSharedMemorySize, SMEM_BYTES);
    cudaFuncSetAttribute(mma_nt<2>, cudaFuncAttributeMaxDynamicSharedMemorySize, SMEM_BYTES);

    const LL M1 = 1048576;  // 1024*1024
    dim3 thr(256);

    // --- prep: merged splits (1 launch) + transpose split ---
    split_all_kernel<<<68608, thr>>>(input, context, W_in, W_out,
                                     in_hi, in_lo, ctx_hi, ctx_lo,
                                     win_hi, win_lo, wo_hi, wo_lo);
    transpose_split_kernel<<<dim3(32, 32, 32), thr>>>(context, ctT_hi, ctT_lo);

    // --- 1. h_t = input @ W_in^T  (M=32768, N=1024) -> split ht ---
    mma_nt<1><<<dim3(8, 256, 1), thr, SMEM_BYTES>>>(
        in_hi, in_lo, 1024, 0,
        win_hi, win_lo, 1024, 0,
        nullptr, nullptr, 0, 0, nullptr, nullptr, 0, 0,
        nullptr, ht_hi, ht_lo, 1024, 0,
        1024, 1);

    // --- 2. align[b] = h_t[b] @ context[b]^T -> fp32 scores ---
    mma_nt<0><<<dim3(8, 8, 32), thr, SMEM_BYTES>>>(
        ht_hi, ht_lo, 1024, M1,
        ctx_hi, ctx_lo, 1024, M1,
        nullptr, nullptr, 0, 0, nullptr, nullptr, 0, 0,
        sc, nullptr, nullptr, 1024, M1,
        1024, 1);

    // --- 3. softmax -> d_out[T,B,S] + split probs ---
    softmax_kernel<<<32 * 1024, thr>>>(sc, out_align, p_hi, p_lo);

    // --- 4. c[b] = probs[b] @ (context[b]^T)^T -> split c ---
    mma_nt<1><<<dim3(8, 8, 32), thr, SMEM_BYTES>>>(
        p_hi, p_lo, 1024, M1,
        ctT_hi, ctT_lo, 1024, M1,
        nullptr, nullptr, 0, 0, nullptr, nullptr, 0, 0,
        nullptr, c_hi, c_lo, 1024, M1,
        1024, 1);

    // --- 5. attn = tanh([c, input] @ W_out^T) -> d_out[T,B,D] ---
    mma_nt<2><<<dim3(8, 8, 32), thr, SMEM_BYTES>>>(
        c_hi, c_lo, 1024, M1,
        wo_hi, wo_lo, 2048, 0,
        in_hi, in_lo, 1024, M1,
        wo_hi + 1024, wo_lo + 1024, 2048, 0,
        out_attn, nullptr, nullptr, 32768, 1024,
        1024, 2);

    (void)in_sizes; (void)n_in; (void)out_size;
}